// round 11
// baseline (speedup 1.0000x reference)
#include <cuda_runtime.h>
#include <math_constants.h>
#include <stdint.h>

#define NTOT     18432
#define TPB      1024
#define TILE     256                 /* j-tile size */
#define NSTRIP   24
#define NOFF     276                 /* C(24,2) */
#define NOFFBLK  138                 /* 2 tiles per block */
#define NDIAGBLK 6                   /* 4 triangles per block */
#define NUNITS   144                 /* partial slots: 6 diag-blk + 138 off-blk */
#define GRID     147                 /* 2 quantile + 1 std + 144 pairwise */
#define NWARPS   32
#define GMAX     1024
#define SELMAX   48
#define NV4      4608                /* NTOT / 4 */
#define SMEM_BYTES 16384             /* diag: 4 tiles * 256 * 16B */

static const double NPAIRS_D = 18871296.0;
static const double RAND_STD = 1.75;
static const double IQR_RAND = 2.45;

__device__ double   g_pair_partial[NUNITS];
__device__ double   g_sum_d, g_sumsq_d;
__device__ float    g_qv[4];
__device__ unsigned g_done = 0;

__device__ __forceinline__ float sqrt_approx(float x) {
    float r; asm("sqrt.approx.f32 %0, %1;" : "=f"(r) : "f"(x)); return r;
}
__device__ __forceinline__ unsigned fkey(float f) {
    unsigned u = __float_as_uint(f);
    return (u & 0x80000000u) ? ~u : (u | 0x80000000u);
}
__device__ __forceinline__ float funkey(unsigned u) {
    unsigned bits = (u & 0x80000000u) ? (u & 0x7fffffffu) : ~u;
    return __uint_as_float(bits);
}
__device__ __forceinline__ void hit(float s, float& acc) {
    if (s < 0.64f) acc += 0.8f - sqrt_approx(fmaxf(s, 0.0f));
}
__device__ __forceinline__ float sqd(float4 o, float R, float A, float B, float C) {
    return fmaf(C, o.z, fmaf(B, o.y, fmaf(A, o.x, R + o.w)));
}

__global__ void __launch_bounds__(TPB, 1)
dp_fused_kernel(const float* __restrict__ g, float* __restrict__ out) {
    extern __shared__ unsigned char smem_raw[];
    const int bid = blockIdx.x;
    const int t   = threadIdx.x;
    const int w   = t >> 5;
    const int ln  = t & 31;

    __shared__ unsigned s_wcnt[NWARPS];
    __shared__ unsigned s_tot, s_gcnt;
    __shared__ float    s_fred[NWARPS];
    __shared__ float    s_q[2];
    __shared__ int      s_last;

    if (bid >= 3 + NDIAGBLK) {
        /* ===== off-diag pairwise block: 2 tiles, 512 threads each ===== */
        const int pb = bid - (3 + NDIAGBLK);      /* 0..137 */
        const int t0 = pb * 2;
        /* decode tile t0 -> (a0, b0); t0+1 follows lexicographically */
        int a0 = 0, rem = t0;
        while (rem >= NSTRIP - 1 - a0) { rem -= NSTRIP - 1 - a0; ++a0; }
        int b0 = a0 + 1 + rem;
        int a1 = a0, b1 = b0 + 1;
        if (b1 >= NSTRIP) { a1 = a0 + 1; b1 = a1 + 1; }

        float4* tj = (float4*)smem_raw;           /* [512]: tile0 | tile1 */
        if (t < 2 * TILE) {
            const int tb = (t >> 8) ? b1 : b0;
            const int j  = tb * TILE + (t & (TILE - 1));
            float xj = g[3 * j + 0], yj = g[3 * j + 1], zj = g[3 * j + 2];
            tj[t] = make_float4(xj, yj, zj,
                                fmaf(zj, zj, fmaf(yj, yj, xj * xj)));
        }
        const int u  = t >> 9;                    /* which tile */
        const int v  = t & 511;
        const int ii = v & (TILE - 1);
        const int jh = v >> 8;                    /* j half: 0 or 1 */
        const int ia = u ? a1 : a0;
        float xi, yi, zi;
        {
            const int i = ia * TILE + ii;
            xi = g[3 * i + 0]; yi = g[3 * i + 1]; zi = g[3 * i + 2];
        }
        __syncthreads();

        const float R = fmaf(zi, zi, fmaf(yi, yi, xi * xi));
        const float A = -2.0f * xi, B = -2.0f * yi, C = -2.0f * zi;
        const float4* tb = tj + u * TILE;
        const int j0 = jh * (TILE / 2);
        const int j1 = j0 + TILE / 2;

        float acc = 0.f;
        #pragma unroll 2
        for (int jj = j0; jj < j1; jj += 4) {
            float s0 = sqd(tb[jj + 0], R, A, B, C);
            float s1 = sqd(tb[jj + 1], R, A, B, C);
            float s2 = sqd(tb[jj + 2], R, A, B, C);
            float s3 = sqd(tb[jj + 3], R, A, B, C);
            float mn = fminf(fminf(s0, s1), fminf(s2, s3));
            if (mn < 0.64f) {
                hit(s0, acc); hit(s1, acc); hit(s2, acc); hit(s3, acc);
            }
        }

        #pragma unroll
        for (int o = 16; o; o >>= 1)
            acc += __shfl_down_sync(0xffffffffu, acc, o);
        if (ln == 0) s_fred[w] = acc;
        __syncthreads();
        if (t == 0) {
            float r = 0.f;
            #pragma unroll
            for (int i2 = 0; i2 < NWARPS; ++i2) r += s_fred[i2];
            g_pair_partial[NDIAGBLK + pb] = (double)r;
        }

    } else if (bid >= 3) {
        /* ===== diag pairwise block: 4 triangles of 256, wrap mapping ===== */
        const int db = bid - 3;                   /* 0..5 */
        const int gq = t >> 8;                    /* triangle 0..3 */
        const int tt = t & (TILE - 1);
        const int strip = db * 4 + gq;

        float4* tj = (float4*)smem_raw;           /* [1024]: 4 triangles */
        {
            const int j = strip * TILE + tt;
            float xj = g[3 * j + 0], yj = g[3 * j + 1], zj = g[3 * j + 2];
            tj[t] = make_float4(xj, yj, zj,
                                fmaf(zj, zj, fmaf(yj, yj, xj * xj)));
        }
        __syncthreads();

        const float4* tb = tj + gq * TILE;
        float4 me = tb[tt];
        const float R = me.w;
        const float A = -2.0f * me.x, B = -2.0f * me.y, C = -2.0f * me.z;

        float acc = 0.f;
        #pragma unroll 1
        for (int d = 1; d <= 124; d += 4) {
            float s0 = sqd(tb[(tt + d)     & (TILE - 1)], R, A, B, C);
            float s1 = sqd(tb[(tt + d + 1) & (TILE - 1)], R, A, B, C);
            float s2 = sqd(tb[(tt + d + 2) & (TILE - 1)], R, A, B, C);
            float s3 = sqd(tb[(tt + d + 3) & (TILE - 1)], R, A, B, C);
            float mn = fminf(fminf(s0, s1), fminf(s2, s3));
            if (mn < 0.64f) {
                hit(s0, acc); hit(s1, acc); hit(s2, acc); hit(s3, acc);
            }
        }
        {   /* d = 125, 126, 127 */
            float s0 = sqd(tb[(tt + 125) & (TILE - 1)], R, A, B, C);
            float s1 = sqd(tb[(tt + 126) & (TILE - 1)], R, A, B, C);
            float s2 = sqd(tb[(tt + 127) & (TILE - 1)], R, A, B, C);
            float mn = fminf(fminf(s0, s1), s2);
            if (mn < 0.64f) { hit(s0, acc); hit(s1, acc); hit(s2, acc); }
        }
        if (tt < TILE / 2) {
            float s0 = sqd(tb[(tt + 128) & (TILE - 1)], R, A, B, C);
            hit(s0, acc);
        }

        #pragma unroll
        for (int o = 16; o; o >>= 1)
            acc += __shfl_down_sync(0xffffffffu, acc, o);
        if (ln == 0) s_fred[w] = acc;
        __syncthreads();
        if (t == 0) {
            float r = 0.f;
            #pragma unroll
            for (int i2 = 0; i2 < NWARPS; ++i2) r += s_fred[i2];
            g_pair_partial[db] = (double)r;
        }

    } else if (bid < 2) {
        /* ========= exact quantile pair (ranks k0, k0+1), 3-phase ========= */
        const int qb = bid;
        const unsigned k0 = qb ? 13823u : 4607u;
        const float gA = qb ? 0.6245f : -0.7245f;
        const float gB = qb ? 0.7245f : -0.6245f;
        const float4* gv4 = (const float4*)g;

        float lo = -CUDART_INF_F, hi = CUDART_INF_F;
        unsigned cL = 0, cH = NTOT;
        bool allEq = false;

        for (int it = 0; it < 48; ++it) {
            if (cH - cL <= (unsigned)GMAX) break;
            const unsigned klo = fkey(lo), khi = fkey(hi);
            if (khi - klo <= 1u) { allEq = true; break; }
            float cand;
            if (it == 0)      cand = gA;
            else if (it == 1) cand = gB;
            else if (it < 8) {
                double frac = ((double)k0 + 0.5 - (double)cL) / (double)(cH - cL);
                cand = (float)((double)lo + frac * ((double)hi - (double)lo));
            } else cand = funkey(klo + (khi - klo) / 2u);
            {
                unsigned kc = fkey(cand);
                if (!(kc > klo && kc < khi)) cand = funkey(klo + (khi - klo) / 2u);
            }
            unsigned c = 0;
            for (int e = t; e < NV4; e += TPB) {
                float4 q = gv4[e];
                c += (q.x < cand) ? 1u : 0u;
                c += (q.y < cand) ? 1u : 0u;
                c += (q.z < cand) ? 1u : 0u;
                c += (q.w < cand) ? 1u : 0u;
            }
            #pragma unroll
            for (int o = 16; o; o >>= 1) c += __shfl_down_sync(0xffffffffu, c, o);
            if (ln == 0) s_wcnt[w] = c;
            __syncthreads();
            if (t == 0) {
                unsigned totc = 0;
                #pragma unroll
                for (int i2 = 0; i2 < NWARPS; ++i2) totc += s_wcnt[i2];
                s_tot = totc;
            }
            __syncthreads();
            const unsigned ctot = s_tot;
            if (ctot <= k0) { lo = cand; cL = ctot; }
            else            { hi = cand; cH = ctot; }
        }

        if (allEq) {
            if (t == 0) { s_q[0] = lo; s_q[1] = lo; }
            __syncthreads();
        } else {
            float* sub = (float*)smem_raw;
            if (t == 0) s_gcnt = 0;
            __syncthreads();
            for (int e = t; e < NV4; e += TPB) {
                float4 q = gv4[e];
                float qq[4] = {q.x, q.y, q.z, q.w};
                #pragma unroll
                for (int c4 = 0; c4 < 4; ++c4) {
                    float x = qq[c4];
                    if (x >= lo && x < hi) {
                        unsigned p = atomicAdd(&s_gcnt, 1u);
                        if (p < (unsigned)GMAX) sub[p] = x;
                    }
                }
            }
            __syncthreads();
            const unsigned mm0 = s_gcnt;
            const unsigned cL0 = cL;

            unsigned cLg = cL, cHg = cH;
            float lo2 = lo, hi2 = hi;
            for (int it = 0; it < 64; ++it) {
                if (cHg - cLg <= (unsigned)SELMAX) break;
                const unsigned klo = fkey(lo2), khi = fkey(hi2);
                if (khi - klo <= 1u) break;
                float cand;
                if (it < 10) {
                    double frac = ((double)k0 + 0.5 - (double)cLg) / (double)(cHg - cLg);
                    cand = (float)((double)lo2 + frac * ((double)hi2 - (double)lo2));
                } else cand = funkey(klo + (khi - klo) / 2u);
                {
                    unsigned kc = fkey(cand);
                    if (!(kc > klo && kc < khi)) cand = funkey(klo + (khi - klo) / 2u);
                }
                unsigned c = (t < (int)mm0) ? ((sub[t] < cand) ? 1u : 0u) : 0u;
                #pragma unroll
                for (int o = 16; o; o >>= 1) c += __shfl_down_sync(0xffffffffu, c, o);
                if (ln == 0) s_wcnt[w] = c;
                __syncthreads();
                if (t == 0) {
                    unsigned totc = 0;
                    #pragma unroll
                    for (int i2 = 0; i2 < NWARPS; ++i2) totc += s_wcnt[i2];
                    s_tot = totc;
                }
                __syncthreads();
                const unsigned cg = cL0 + s_tot;
                if (cg <= k0) { lo2 = cand; cLg = cg; }
                else          { hi2 = cand; cHg = cg; }
            }

            if (t < (int)mm0) {
                float x = sub[t];
                if (x >= lo2 && x < hi2) {
                    unsigned cl = 0, ce = 0;
                    for (unsigned jj = 0; jj < mm0; ++jj) {
                        float y = sub[jj];
                        cl += (y < x) ? 1u : 0u;
                        ce += (y == x) ? 1u : 0u;
                    }
                    const unsigned glo = cL0 + cl;
                    if (glo <= k0 && k0 < glo + ce)           s_q[0] = x;
                    if (glo <= k0 + 1u && k0 + 1u < glo + ce) s_q[1] = x;
                }
            }
            if (k0 + 1u >= cHg) {
                float mn = CUDART_INF_F;
                for (int e = t; e < NV4; e += TPB) {
                    float4 q = gv4[e];
                    if (q.x >= hi2) mn = fminf(mn, q.x);
                    if (q.y >= hi2) mn = fminf(mn, q.y);
                    if (q.z >= hi2) mn = fminf(mn, q.z);
                    if (q.w >= hi2) mn = fminf(mn, q.w);
                }
                #pragma unroll
                for (int o = 16; o; o >>= 1)
                    mn = fminf(mn, __shfl_down_sync(0xffffffffu, mn, o));
                if (ln == 0) s_fred[w] = mn;
                __syncthreads();
                if (t == 0) {
                    float r = s_fred[0];
                    #pragma unroll
                    for (int i2 = 1; i2 < NWARPS; ++i2) r = fminf(r, s_fred[i2]);
                    s_q[1] = r;
                }
            }
            __syncthreads();
        }
        if (t == 0) {
            g_qv[2 * qb + 0] = s_q[0];
            g_qv[2 * qb + 1] = s_q[1];
        }

    } else {
        /* ============ std sums (fp64, deterministic) ============ */
        __shared__ double sds[NWARPS], sdq[NWARPS];
        const float4* gv4 = (const float4*)g;
        double s = 0.0, s2 = 0.0;
        for (int e = t; e < NV4; e += TPB) {
            float4 q = gv4[e];
            double x0 = (double)q.x, x1 = (double)q.y;
            double x2 = (double)q.z, x3 = (double)q.w;
            s  += (x0 + x1) + (x2 + x3);
            s2 += (x0 * x0 + x1 * x1) + (x2 * x2 + x3 * x3);
        }
        #pragma unroll
        for (int o = 16; o; o >>= 1) {
            s  += __shfl_down_sync(0xffffffffu, s,  o);
            s2 += __shfl_down_sync(0xffffffffu, s2, o);
        }
        if (ln == 0) { sds[w] = s; sdq[w] = s2; }
        __syncthreads();
        if (t == 0) {
            double aa = 0.0, bb = 0.0;
            #pragma unroll
            for (int i2 = 0; i2 < NWARPS; ++i2) { aa += sds[i2]; bb += sdq[i2]; }
            g_sum_d = aa; g_sumsq_d = bb;
        }
    }

    /* ====== epilogue: thread-0 release; last block combines ====== */
    __syncthreads();
    if (t == 0) {
        __threadfence();
        unsigned old = atomicAdd(&g_done, 1u);
        s_last = (old == (unsigned)(GRID - 1)) ? 1 : 0;
    }
    __syncthreads();
    if (s_last) {
        if (t < 32) {
            __threadfence();
            double s = 0.0;
            for (int i2 = t; i2 < NUNITS; i2 += 32) s += g_pair_partial[i2];
            #pragma unroll
            for (int o = 16; o; o >>= 1) s += __shfl_down_sync(0xffffffffu, s, o);
            if (t == 0) {
                double punish = s / NPAIRS_D;
                double var = (g_sumsq_d - g_sum_d * g_sum_d / (double)NTOT)
                             / (double)(NTOT - 1);
                double sd = sqrt(var);
                float q1 = 0.25f * g_qv[0] + 0.75f * g_qv[1];
                float q3 = 0.75f * g_qv[2] + 0.25f * g_qv[3];
                double dstd = sd - RAND_STD;
                double diqr = (double)(q3 - q1) - IQR_RAND;
                out[0] = (float)(punish + dstd * dstd + diqr * diqr);
                g_done = 0;   /* reset for next graph replay */
            }
        }
    }
}

extern "C" void kernel_launch(void* const* d_in, const int* in_sizes, int n_in,
                              void* d_out, int out_size) {
    (void)in_sizes; (void)n_in; (void)out_size;
    const float* g = (const float*)d_in[0];
    float* out = (float*)d_out;
    dp_fused_kernel<<<GRID, TPB, SMEM_BYTES>>>(g, out);
}